// round 1
// baseline (speedup 1.0000x reference)
#include <cuda_runtime.h>
#include <math.h>

// Problem constants
#define N_   8
#define A_   16368
#define K_   200
#define B_   20
#define P_   4
#define PIX  16384            // 128*128
#define G_   8                // k-values per block (proto reuse factor)
#define GRP  (K_ / G_)        // 25
#define CH_  4                // pixel chunks per (n, k-group)
#define CHPIX (PIX / CH_)     // 4096
#define NBLK (N_ * GRP * CH_) // 800
#define T1   256              // threads, mask kernel
#define T2   1024             // threads, finish kernel

__device__ float g_partials[NBLK];

__device__ __forceinline__ float ex2f_(float x) {
    float r; asm("ex2.approx.ftz.f32 %0, %1;" : "=f"(r) : "f"(x)); return r;
}
__device__ __forceinline__ float lg2f_(float x) {
    float r; asm("lg2.approx.ftz.f32 %0, %1;" : "=f"(r) : "f"(x)); return r;
}

// BCE(sigmoid(x), y) = ln2 * ( log2(1 + 2^(-|z|)) + max(z,0) - y*z ),  z = x*log2e
// (clip at p in [1e-7, 1-1e-7] only matters for |x| > 16.1 — probability ~0 for
//  these N(0,1)-scale logits; omitted error per element < 1.2e-7, vanishes in the mean)
__device__ __forceinline__ float bce2(float z, float y) {
    float w = lg2f_(1.0f + ex2f_(-fabsf(z)));
    return w + fmaxf(z, 0.0f) - y * z;   // scaled by ln2 once at the end
}

__global__ __launch_bounds__(T1)
void mask_loss_kernel(const float* __restrict__ map_coef,
                      const float* __restrict__ proto,
                      const float* __restrict__ gt_masks,
                      const int*   __restrict__ pos_idx,
                      const int*   __restrict__ gt_idx)
{
    const float LOG2E = 1.4426950408889634f;
    const int bid = blockIdx.x;
    const int n   = bid / (GRP * CH_);
    const int rem = bid % (GRP * CH_);
    const int kg  = rem / CH_;
    const int ch  = rem % CH_;
    const int tid = threadIdx.x;

    // Per-block: 8 coefficient sets (pre-scaled by log2e) + 8 goal-mask pointers
    float c0[G_], c1[G_], c2[G_], c3[G_];
    const float* goal[G_];
#pragma unroll
    for (int g = 0; g < G_; ++g) {
        int k = kg * G_ + g;
        int a = pos_idx[n * K_ + k];
        const float* cp = map_coef + ((size_t)n * A_ + a) * P_;
        c0[g] = cp[0] * LOG2E; c1[g] = cp[1] * LOG2E;
        c2[g] = cp[2] * LOG2E; c3[g] = cp[3] * LOG2E;
        int b = gt_idx[n * K_ + k];
        goal[g] = gt_masks + ((size_t)n * B_ + b) * PIX;
    }
    const float* pb = proto + (size_t)n * P_ * PIX;

    float acc = 0.0f;
#pragma unroll
    for (int it = 0; it < CHPIX / (T1 * 4); ++it) {          // 4 iterations
        int pix = ch * CHPIX + (it * T1 + tid) * 4;
        float4 p0 = *(const float4*)(pb + 0 * PIX + pix);
        float4 p1 = *(const float4*)(pb + 1 * PIX + pix);
        float4 p2 = *(const float4*)(pb + 2 * PIX + pix);
        float4 p3 = *(const float4*)(pb + 3 * PIX + pix);
#pragma unroll
        for (int g = 0; g < G_; ++g) {
            float4 y = *(const float4*)(goal[g] + pix);
            float zx = fmaf(c0[g], p0.x, fmaf(c1[g], p1.x, fmaf(c2[g], p2.x, c3[g] * p3.x)));
            float zy = fmaf(c0[g], p0.y, fmaf(c1[g], p1.y, fmaf(c2[g], p2.y, c3[g] * p3.y)));
            float zz = fmaf(c0[g], p0.z, fmaf(c1[g], p1.z, fmaf(c2[g], p2.z, c3[g] * p3.z)));
            float zw = fmaf(c0[g], p0.w, fmaf(c1[g], p1.w, fmaf(c2[g], p2.w, c3[g] * p3.w)));
            acc += bce2(zx, y.x);
            acc += bce2(zy, y.y);
            acc += bce2(zz, y.z);
            acc += bce2(zw, y.w);
        }
    }

    __shared__ float red[T1];
    red[tid] = acc;
    __syncthreads();
#pragma unroll
    for (int s = T1 / 2; s > 0; s >>= 1) {
        if (tid < s) red[tid] += red[tid + s];
        __syncthreads();
    }
    if (tid == 0) g_partials[bid] = red[0];
}

__global__ __launch_bounds__(T2)
void finish_kernel(const float* __restrict__ map_class,
                   const float* __restrict__ map_box,
                   const float* __restrict__ anchor_center,
                   const float* __restrict__ anchor_hw,
                   const float* __restrict__ gt_boxes,
                   const int*   __restrict__ pos_idx,
                   const int*   __restrict__ neg_idx,
                   const int*   __restrict__ gt_idx,
                   float*       __restrict__ out)
{
    const int tid = threadIdx.x;
    const float LN2 = 0.6931471805599453f;
    const float EPS = 1e-7f;
    float s = 0.0f;

    // mask partials: weight = ln2 / (PIX * N * K)
    const float wm = LN2 / ((float)PIX * (float)N_ * (float)K_);
    for (int i = tid; i < NBLK; i += T2) s += g_partials[i] * wm;

    // classification, positives vs 1: weight 1/(N*K*K)
    const float wp = 1.0f / ((float)N_ * K_ * K_);
    for (int i = tid; i < N_ * K_; i += T2) {
        int n = i / K_;
        int a = pos_idx[i];
        float p = map_class[n * A_ + a];
        p = fminf(fmaxf(p, EPS), 1.0f - EPS);
        s += -logf(p) * wp;
    }
    // classification, negatives vs 0: weight 1/(N*3K*K)
    const float wn = 1.0f / ((float)N_ * 3.0f * K_ * K_);
    for (int i = tid; i < N_ * 3 * K_; i += T2) {
        int n = i / (3 * K_);
        int a = neg_idx[i];
        float p = map_class[n * A_ + a];
        p = fminf(fmaxf(p, EPS), 1.0f - EPS);
        s += -log1pf(-p) * wn;
    }
    // localization SmoothL1: weight 1/(N*K)
    const float wl = 1.0f / ((float)N_ * K_);
    for (int i = tid; i < N_ * K_; i += T2) {
        int n  = i / K_;
        int a  = pos_idx[i];
        int gi = gt_idx[i];
        const float* pr = map_box + ((size_t)n * A_ + a) * 4;
        const float* gt = gt_boxes + ((size_t)n * B_ + gi) * 4;
        float ac0 = anchor_center[a * 2 + 0];
        float ac1 = anchor_center[a * 2 + 1];
        float ah  = anchor_hw[a * 2 + 0];
        float aw  = anchor_hw[a * 2 + 1];
        float t0 = (gt[0] - ac0) / ah;
        float t1 = (gt[1] - ac1) / aw;
        float t2 = log10f(gt[2] / ah);
        float t3 = log10f(gt[3] / aw);
        float d, ad, l = 0.0f;
        d = pr[0] - t0; ad = fabsf(d); l += (ad < 1.0f) ? 0.5f * d * d : ad - 0.5f;
        d = pr[1] - t1; ad = fabsf(d); l += (ad < 1.0f) ? 0.5f * d * d : ad - 0.5f;
        d = pr[2] - t2; ad = fabsf(d); l += (ad < 1.0f) ? 0.5f * d * d : ad - 0.5f;
        d = pr[3] - t3; ad = fabsf(d); l += (ad < 1.0f) ? 0.5f * d * d : ad - 0.5f;
        s += l * wl;
    }

    __shared__ float red[T2];
    red[tid] = s;
    __syncthreads();
#pragma unroll
    for (int st = T2 / 2; st > 0; st >>= 1) {
        if (tid < st) red[tid] += red[tid + st];
        __syncthreads();
    }
    if (tid == 0) out[0] = red[0];
}

extern "C" void kernel_launch(void* const* d_in, const int* in_sizes, int n_in,
                              void* d_out, int out_size)
{
    const float* map_class     = (const float*)d_in[0];
    const float* map_box       = (const float*)d_in[1];
    const float* map_coef      = (const float*)d_in[2];
    const float* proto         = (const float*)d_in[3];
    const float* anchor_center = (const float*)d_in[4];
    const float* anchor_hw     = (const float*)d_in[5];
    const float* gt_boxes      = (const float*)d_in[6];
    const float* gt_masks      = (const float*)d_in[7];
    const int*   pos_idx       = (const int*)d_in[8];
    const int*   neg_idx       = (const int*)d_in[9];
    const int*   gt_idx        = (const int*)d_in[10];
    float* out = (float*)d_out;

    mask_loss_kernel<<<NBLK, T1>>>(map_coef, proto, gt_masks, pos_idx, gt_idx);
    finish_kernel<<<1, T2>>>(map_class, map_box, anchor_center, anchor_hw,
                             gt_boxes, pos_idx, neg_idx, gt_idx, out);
}

// round 2
// speedup vs baseline: 1.1729x; 1.1729x over previous
#include <cuda_runtime.h>
#include <math.h>

// Problem constants
#define N_    8
#define A_    16368
#define K_    200
#define B_    20
#define PIX   16384           // 128*128
#define G_    8               // k-values per main block
#define GRP   (K_ / G_)       // 25
#define CH_   4               // pixel chunks per (n, k-group)
#define CHPIX (PIX / CH_)     // 4096
#define NB_MAIN (N_ * GRP * CH_)   // 800
#define NB_Y    (N_ * 8)           // 64  (n x 8 pixel-chunks of 2048)
#define NB_MISC (N_)               // 8   (cls + loc per image)
#define NPART   (NB_MAIN + NB_Y + NB_MISC)  // 872
#define T1    256

__device__ float g_partials[NPART];
__device__ unsigned int g_count;   // zero-init; reset to 0 by last block each call

__device__ __forceinline__ float ex2f_(float x) {
    float r; asm("ex2.approx.ftz.f32 %0, %1;" : "=f"(r) : "f"(x)); return r;
}
__device__ __forceinline__ float lg2f_(float x) {
    float r; asm("lg2.approx.ftz.f32 %0, %1;" : "=f"(r) : "f"(x)); return r;
}

// Compile-time weights
#define LOG2E   1.4426950408889634f
#define LN2     0.6931471805599453f
#define LOG10_2 0.3010299956639812f
#define WM  (LN2 / ((float)PIX * (float)N_ * (float)K_))     // mask BCE weight
#define WP  (1.0f / ((float)N_ * K_ * K_))                    // cls pos
#define WN  (1.0f / ((float)N_ * 3.0f * K_ * K_))             // cls neg
#define WL  (1.0f / ((float)N_ * K_))                         // loc

__global__ __launch_bounds__(T1)
void allloss_kernel(const float* __restrict__ map_class,
                    const float* __restrict__ map_box,
                    const float* __restrict__ map_coef,
                    const float* __restrict__ proto,
                    const float* __restrict__ anchor_center,
                    const float* __restrict__ anchor_hw,
                    const float* __restrict__ gt_boxes,
                    const float* __restrict__ gt_masks,
                    const int*   __restrict__ pos_idx,
                    const int*   __restrict__ neg_idx,
                    const int*   __restrict__ gt_idx,
                    float*       __restrict__ out)
{
    const int bid = blockIdx.x;
    const int tid = threadIdx.x;

    __shared__ float red[T1];
    __shared__ float ck[K_][4];   // y-term blocks only
    __shared__ int   bk[K_];
    __shared__ float Cb[B_][4];

    float partial = 0.0f;

    if (bid < NB_MAIN) {
        // ============ main mask term: sum over (n,k,pix) of softplus2 part ============
        const int n   = bid / (GRP * CH_);
        const int rem = bid % (GRP * CH_);
        const int kg  = rem / CH_;
        const int ch  = rem % CH_;

        float c0[G_], c1[G_], c2[G_], c3[G_];
#pragma unroll
        for (int g = 0; g < G_; ++g) {
            int k = kg * G_ + g;
            int a = pos_idx[n * K_ + k];
            const float* cp = map_coef + ((size_t)n * A_ + a) * 4;
            c0[g] = cp[0] * LOG2E; c1[g] = cp[1] * LOG2E;
            c2[g] = cp[2] * LOG2E; c3[g] = cp[3] * LOG2E;
        }
        const float* pb = proto + (size_t)n * 4 * PIX;

        float acc = 0.0f;
#pragma unroll
        for (int it = 0; it < CHPIX / (T1 * 4); ++it) {    // 4 iterations
            int pix = ch * CHPIX + (it * T1 + tid) * 4;
            float4 p0 = *(const float4*)(pb + 0 * PIX + pix);
            float4 p1 = *(const float4*)(pb + 1 * PIX + pix);
            float4 p2 = *(const float4*)(pb + 2 * PIX + pix);
            float4 p3 = *(const float4*)(pb + 3 * PIX + pix);
#pragma unroll
            for (int g = 0; g < G_; ++g) {
                float zx = fmaf(c0[g], p0.x, fmaf(c1[g], p1.x, fmaf(c2[g], p2.x, c3[g] * p3.x)));
                float zy = fmaf(c0[g], p0.y, fmaf(c1[g], p1.y, fmaf(c2[g], p2.y, c3[g] * p3.y)));
                float zz = fmaf(c0[g], p0.z, fmaf(c1[g], p1.z, fmaf(c2[g], p2.z, c3[g] * p3.z)));
                float zw = fmaf(c0[g], p0.w, fmaf(c1[g], p1.w, fmaf(c2[g], p2.w, c3[g] * p3.w)));
                acc += lg2f_(1.0f + ex2f_(-fabsf(zx))) + fmaxf(zx, 0.0f);
                acc += lg2f_(1.0f + ex2f_(-fabsf(zy))) + fmaxf(zy, 0.0f);
                acc += lg2f_(1.0f + ex2f_(-fabsf(zz))) + fmaxf(zz, 0.0f);
                acc += lg2f_(1.0f + ex2f_(-fabsf(zw))) + fmaxf(zw, 0.0f);
            }
        }
        partial = acc * WM;

    } else if (bid < NB_MAIN + NB_Y) {
        // ============ y-term: -sum_pix sum_b y_b(pix) * (C_b . p(pix)) ============
        const int b2  = bid - NB_MAIN;
        const int n   = b2 >> 3;
        const int ch8 = b2 & 7;

        if (tid < K_) {
            int a = pos_idx[n * K_ + tid];
            const float* cp = map_coef + ((size_t)n * A_ + a) * 4;
            ck[tid][0] = cp[0] * LOG2E; ck[tid][1] = cp[1] * LOG2E;
            ck[tid][2] = cp[2] * LOG2E; ck[tid][3] = cp[3] * LOG2E;
            bk[tid] = gt_idx[n * K_ + tid];
        }
        __syncthreads();
        if (tid < B_ * 4) {
            int b = tid >> 2, j = tid & 3;
            float s = 0.0f;
            for (int k = 0; k < K_; ++k)
                if (bk[k] == b) s += ck[k][j];
            Cb[b][j] = s;
        }
        __syncthreads();

        const float* pb = proto + (size_t)n * 4 * PIX;
        const float* gm = gt_masks + (size_t)n * B_ * PIX;
        float acc = 0.0f;
#pragma unroll
        for (int it = 0; it < 2; ++it) {       // 2048 pixels / (256 threads * 4)
            int pix = ch8 * 2048 + (it * T1 + tid) * 4;
            float4 p0 = *(const float4*)(pb + 0 * PIX + pix);
            float4 p1 = *(const float4*)(pb + 1 * PIX + pix);
            float4 p2 = *(const float4*)(pb + 2 * PIX + pix);
            float4 p3 = *(const float4*)(pb + 3 * PIX + pix);
#pragma unroll
            for (int b = 0; b < B_; ++b) {
                float4 y = *(const float4*)(gm + (size_t)b * PIX + pix);
                float cb0 = Cb[b][0], cb1 = Cb[b][1], cb2 = Cb[b][2], cb3 = Cb[b][3];
                float Zx = fmaf(cb0, p0.x, fmaf(cb1, p1.x, fmaf(cb2, p2.x, cb3 * p3.x)));
                float Zy = fmaf(cb0, p0.y, fmaf(cb1, p1.y, fmaf(cb2, p2.y, cb3 * p3.y)));
                float Zz = fmaf(cb0, p0.z, fmaf(cb1, p1.z, fmaf(cb2, p2.z, cb3 * p3.z)));
                float Zw = fmaf(cb0, p0.w, fmaf(cb1, p1.w, fmaf(cb2, p2.w, cb3 * p3.w)));
                acc = fmaf(y.x, Zx, acc);
                acc = fmaf(y.y, Zy, acc);
                acc = fmaf(y.z, Zz, acc);
                acc = fmaf(y.w, Zw, acc);
            }
        }
        partial = -acc * WM;

    } else {
        // ============ cls (pos + neg) and loc for one image ============
        const int n = bid - NB_MAIN - NB_Y;
        const float EPS = 1e-7f;
        float s = 0.0f;

        if (tid < K_) {
            // cls positive: -log(p)
            int a = pos_idx[n * K_ + tid];
            float p = map_class[n * A_ + a];
            p = fminf(fmaxf(p, EPS), 1.0f - EPS);
            s += -lg2f_(p) * (LN2 * WP);

            // localization SmoothL1
            int gi = gt_idx[n * K_ + tid];
            const float* pr = map_box + ((size_t)n * A_ + a) * 4;
            const float* gt = gt_boxes + ((size_t)n * B_ + gi) * 4;
            float ac0 = anchor_center[a * 2 + 0];
            float ac1 = anchor_center[a * 2 + 1];
            float ah  = anchor_hw[a * 2 + 0];
            float aw  = anchor_hw[a * 2 + 1];
            float t0 = (gt[0] - ac0) / ah;
            float t1 = (gt[1] - ac1) / aw;
            float t2 = lg2f_(gt[2] / ah) * LOG10_2;
            float t3 = lg2f_(gt[3] / aw) * LOG10_2;
            float d, ad, l = 0.0f;
            d = pr[0] - t0; ad = fabsf(d); l += (ad < 1.0f) ? 0.5f * d * d : ad - 0.5f;
            d = pr[1] - t1; ad = fabsf(d); l += (ad < 1.0f) ? 0.5f * d * d : ad - 0.5f;
            d = pr[2] - t2; ad = fabsf(d); l += (ad < 1.0f) ? 0.5f * d * d : ad - 0.5f;
            d = pr[3] - t3; ad = fabsf(d); l += (ad < 1.0f) ? 0.5f * d * d : ad - 0.5f;
            s += l * WL;
        }
        // cls negatives: -log(1-p)
        for (int i = tid; i < 3 * K_; i += T1) {
            int a = neg_idx[n * 3 * K_ + i];
            float p = map_class[n * A_ + a];
            p = fminf(fmaxf(p, EPS), 1.0f - EPS);
            s += -lg2f_(1.0f - p) * (LN2 * WN);
        }
        partial = s;
    }

    // ============ block reduction ============
    red[tid] = partial;
    __syncthreads();
#pragma unroll
    for (int st = T1 / 2; st > 0; st >>= 1) {
        if (tid < st) red[tid] += red[tid + st];
        __syncthreads();
    }
    if (tid == 0) g_partials[bid] = red[0];

    // ============ last-block final reduction ============
    __shared__ bool isLast;
    if (tid == 0) {
        __threadfence();
        unsigned int old = atomicAdd(&g_count, 1u);
        isLast = (old == NPART - 1);
    }
    __syncthreads();
    if (isLast) {
        float s = 0.0f;
        for (int i = tid; i < NPART; i += T1) s += g_partials[i];
        red[tid] = s;
        __syncthreads();
#pragma unroll
        for (int st = T1 / 2; st > 0; st >>= 1) {
            if (tid < st) red[tid] += red[tid + st];
            __syncthreads();
        }
        if (tid == 0) {
            out[0] = red[0];
            g_count = 0;   // reset for next graph replay
        }
    }
}

extern "C" void kernel_launch(void* const* d_in, const int* in_sizes, int n_in,
                              void* d_out, int out_size)
{
    const float* map_class     = (const float*)d_in[0];
    const float* map_box       = (const float*)d_in[1];
    const float* map_coef      = (const float*)d_in[2];
    const float* proto         = (const float*)d_in[3];
    const float* anchor_center = (const float*)d_in[4];
    const float* anchor_hw     = (const float*)d_in[5];
    const float* gt_boxes      = (const float*)d_in[6];
    const float* gt_masks      = (const float*)d_in[7];
    const int*   pos_idx       = (const int*)d_in[8];
    const int*   neg_idx       = (const int*)d_in[9];
    const int*   gt_idx        = (const int*)d_in[10];
    float* out = (float*)d_out;

    allloss_kernel<<<NPART, T1>>>(map_class, map_box, map_coef, proto,
                                  anchor_center, anchor_hw, gt_boxes, gt_masks,
                                  pos_idx, neg_idx, gt_idx, out);
}

// round 3
// speedup vs baseline: 1.4725x; 1.2554x over previous
#include <cuda_runtime.h>
#include <math.h>

// Problem constants
#define N_    8
#define A_    16368
#define K_    200
#define B_    20
#define PIX   16384           // 128*128
#define G_    8               // k-values per main block
#define GRP   (K_ / G_)       // 25
#define CH_   4               // pixel chunks per (n, k-group)
#define CHPIX (PIX / CH_)     // 4096
#define NB_MAIN (N_ * GRP * CH_)   // 800
#define NB_Y    (N_ * 8)           // 64
#define NB_MISC (N_)               // 8
#define NPART   (NB_MAIN + NB_Y + NB_MISC)  // 872
#define T1    256

__device__ float g_partials[NPART];
__device__ unsigned int g_count;   // zero-init; reset by final block each call

typedef unsigned long long u64;

__device__ __forceinline__ float ex2f_(float x) {
    float r; asm("ex2.approx.ftz.f32 %0, %1;" : "=f"(r) : "f"(x)); return r;
}
__device__ __forceinline__ float lg2f_(float x) {
    float r; asm("lg2.approx.ftz.f32 %0, %1;" : "=f"(r) : "f"(x)); return r;
}
// packed f32x2 ops (Blackwell FFMA2 path — PTX-only)
__device__ __forceinline__ u64 fma2_(u64 a, u64 b, u64 c) {
    u64 r; asm("fma.rn.f32x2 %0, %1, %2, %3;" : "=l"(r) : "l"(a), "l"(b), "l"(c)); return r;
}
__device__ __forceinline__ u64 mul2_(u64 a, u64 b) {
    u64 r; asm("mul.rn.f32x2 %0, %1, %2;" : "=l"(r) : "l"(a), "l"(b)); return r;
}
__device__ __forceinline__ u64 add2_(u64 a, u64 b) {
    u64 r; asm("add.rn.f32x2 %0, %1, %2;" : "=l"(r) : "l"(a), "l"(b)); return r;
}
__device__ __forceinline__ void unpack2_(u64 v, float& a, float& b) {
    unsigned lo, hi;
    asm("mov.b64 {%0, %1}, %2;" : "=r"(lo), "=r"(hi) : "l"(v));
    a = __uint_as_float(lo); b = __uint_as_float(hi);
}

#define LOG2E   1.4426950408889634f
#define LN2     0.6931471805599453f
#define LOG10_2 0.3010299956639812f
#define WM  (LN2 / ((float)PIX * (float)N_ * (float)K_))
#define WP  (1.0f / ((float)N_ * K_ * K_))
#define WN  (1.0f / ((float)N_ * 3.0f * K_ * K_))
#define WL  (1.0f / ((float)N_ * K_))

__global__ __launch_bounds__(T1, 2)
void allloss_kernel(const float* __restrict__ map_class,
                    const float* __restrict__ map_box,
                    const float* __restrict__ map_coef,
                    const float* __restrict__ proto,
                    const float* __restrict__ anchor_center,
                    const float* __restrict__ anchor_hw,
                    const float* __restrict__ gt_boxes,
                    const float* __restrict__ gt_masks,
                    const int*   __restrict__ pos_idx,
                    const int*   __restrict__ neg_idx,
                    const int*   __restrict__ gt_idx,
                    float*       __restrict__ out)
{
    const int bid = blockIdx.x;
    const int tid = threadIdx.x;

    __shared__ float  red[T1];
    __shared__ float2 cpair[G_][4];   // main blocks: packed {c,c} coefficients
    __shared__ float  ck[K_][4];      // y blocks
    __shared__ int    bk[K_];
    __shared__ float  Cb[B_][4];
    __shared__ float  Ct[4];

    float partial = 0.0f;

    if (bid < NB_MAIN) {
        // ===== main mask term: sum of lg2(1+2^-|z|) + 0.5*|z|  (0.5*z handled in y-blocks) =====
        const int n   = bid / (GRP * CH_);
        const int rem = bid % (GRP * CH_);
        const int kg  = rem / CH_;
        const int ch  = rem % CH_;

        if (tid < G_ * 4) {
            int g = tid >> 2, j = tid & 3;
            int a = pos_idx[n * K_ + kg * G_ + g];
            float v = map_coef[((size_t)n * A_ + a) * 4 + j] * LOG2E;
            cpair[g][j] = make_float2(v, v);
        }
        __syncthreads();

        const float* pb = proto + (size_t)n * 4 * PIX;
        u64   accA   = 0ull;      // packed |z| accumulator (two halves)
        float acc_lg = 0.0f;

#pragma unroll 1
        for (int it = 0; it < CHPIX / (T1 * 4); ++it) {    // 4 iterations
            int pix = ch * CHPIX + (it * T1 + tid) * 4;
            ulonglong2 q0 = *(const ulonglong2*)(pb + 0 * PIX + pix);
            ulonglong2 q1 = *(const ulonglong2*)(pb + 1 * PIX + pix);
            ulonglong2 q2 = *(const ulonglong2*)(pb + 2 * PIX + pix);
            ulonglong2 q3 = *(const ulonglong2*)(pb + 3 * PIX + pix);
#pragma unroll
            for (int g0 = 0; g0 < G_; ++g0) {
                int g = (g0 + it) & (G_ - 1);   // rotation: defeats cross-it hoisting; sum over g invariant
                const u64* cp = (const u64*)cpair[g];
                u64 C0 = cp[0], C1 = cp[1], C2 = cp[2], C3 = cp[3];
                u64 zA = fma2_(C0, q0.x, fma2_(C1, q1.x, fma2_(C2, q2.x, mul2_(C3, q3.x))));
                u64 zB = fma2_(C0, q0.y, fma2_(C1, q1.y, fma2_(C2, q2.y, mul2_(C3, q3.y))));
                u64 aA = zA & 0x7fffffff7fffffffULL;
                u64 aB = zB & 0x7fffffff7fffffffULL;
                accA = add2_(accA, aA);
                accA = add2_(accA, aB);
                float a0, a1, a2, a3;
                unpack2_(aA, a0, a1);
                unpack2_(aB, a2, a3);
                float v0 = 1.0f + ex2f_(-a0);
                float v1 = 1.0f + ex2f_(-a1);
                float v2 = 1.0f + ex2f_(-a2);
                float v3 = 1.0f + ex2f_(-a3);
                acc_lg += lg2f_((v0 * v1) * (v2 * v3));   // one LG2 per 4 elements
            }
        }
        float ax, ay;
        unpack2_(accA, ax, ay);
        partial = (acc_lg + 0.5f * (ax + ay)) * WM;

    } else if (bid < NB_MAIN + NB_Y) {
        // ===== y-term and 0.5*Sum z term:  sum_pix [ 0.5*(Ctot.p) - sum_b y_b*(C_b.p) ] =====
        const int b2  = bid - NB_MAIN;
        const int n   = b2 >> 3;
        const int ch8 = b2 & 7;

        if (tid < K_) {
            int a = pos_idx[n * K_ + tid];
            const float* cp = map_coef + ((size_t)n * A_ + a) * 4;
            ck[tid][0] = cp[0] * LOG2E; ck[tid][1] = cp[1] * LOG2E;
            ck[tid][2] = cp[2] * LOG2E; ck[tid][3] = cp[3] * LOG2E;
            bk[tid] = gt_idx[n * K_ + tid];
        }
        __syncthreads();
        if (tid < B_ * 4) {
            int b = tid >> 2, j = tid & 3;
            float s = 0.0f;
            for (int k = 0; k < K_; ++k)
                if (bk[k] == b) s += ck[k][j];
            Cb[b][j] = s;
        }
        __syncthreads();
        if (tid < 4) {
            float s = 0.0f;
            for (int b = 0; b < B_; ++b) s += Cb[b][tid];
            Ct[tid] = s;
        }
        __syncthreads();

        const float* pb = proto + (size_t)n * 4 * PIX;
        const float* gm = gt_masks + (size_t)n * B_ * PIX;
        float accD = 0.0f, accE = 0.0f;
#pragma unroll
        for (int it = 0; it < 2; ++it) {
            int pix = ch8 * 2048 + (it * T1 + tid) * 4;
            float4 p0 = *(const float4*)(pb + 0 * PIX + pix);
            float4 p1 = *(const float4*)(pb + 1 * PIX + pix);
            float4 p2 = *(const float4*)(pb + 2 * PIX + pix);
            float4 p3 = *(const float4*)(pb + 3 * PIX + pix);
            // E = Ctot . p  (for the 0.5*Sum z correction)
            float t0 = Ct[0], t1 = Ct[1], t2 = Ct[2], t3 = Ct[3];
            accE += fmaf(t0, p0.x, fmaf(t1, p1.x, fmaf(t2, p2.x, t3 * p3.x)));
            accE += fmaf(t0, p0.y, fmaf(t1, p1.y, fmaf(t2, p2.y, t3 * p3.y)));
            accE += fmaf(t0, p0.z, fmaf(t1, p1.z, fmaf(t2, p2.z, t3 * p3.z)));
            accE += fmaf(t0, p0.w, fmaf(t1, p1.w, fmaf(t2, p2.w, t3 * p3.w)));
#pragma unroll
            for (int b = 0; b < B_; ++b) {
                float4 y = *(const float4*)(gm + (size_t)b * PIX + pix);
                float cb0 = Cb[b][0], cb1 = Cb[b][1], cb2 = Cb[b][2], cb3 = Cb[b][3];
                float Zx = fmaf(cb0, p0.x, fmaf(cb1, p1.x, fmaf(cb2, p2.x, cb3 * p3.x)));
                float Zy = fmaf(cb0, p0.y, fmaf(cb1, p1.y, fmaf(cb2, p2.y, cb3 * p3.y)));
                float Zz = fmaf(cb0, p0.z, fmaf(cb1, p1.z, fmaf(cb2, p2.z, cb3 * p3.z)));
                float Zw = fmaf(cb0, p0.w, fmaf(cb1, p1.w, fmaf(cb2, p2.w, cb3 * p3.w)));
                accD = fmaf(y.x, Zx, accD);
                accD = fmaf(y.y, Zy, accD);
                accD = fmaf(y.z, Zz, accD);
                accD = fmaf(y.w, Zw, accD);
            }
        }
        partial = (0.5f * accE - accD) * WM;

    } else {
        // ===== cls (pos+neg) + loc for one image =====
        const int n = bid - NB_MAIN - NB_Y;
        const float EPS = 1e-7f;
        float s = 0.0f;

        if (tid < K_) {
            int a = pos_idx[n * K_ + tid];
            float p = map_class[n * A_ + a];
            p = fminf(fmaxf(p, EPS), 1.0f - EPS);
            s += -lg2f_(p) * (LN2 * WP);

            int gi = gt_idx[n * K_ + tid];
            const float* pr = map_box + ((size_t)n * A_ + a) * 4;
            const float* gt = gt_boxes + ((size_t)n * B_ + gi) * 4;
            float ac0 = anchor_center[a * 2 + 0];
            float ac1 = anchor_center[a * 2 + 1];
            float ah  = anchor_hw[a * 2 + 0];
            float aw  = anchor_hw[a * 2 + 1];
            float t0 = (gt[0] - ac0) / ah;
            float t1 = (gt[1] - ac1) / aw;
            float t2 = lg2f_(gt[2] / ah) * LOG10_2;
            float t3 = lg2f_(gt[3] / aw) * LOG10_2;
            float d, ad, l = 0.0f;
            d = pr[0] - t0; ad = fabsf(d); l += (ad < 1.0f) ? 0.5f * d * d : ad - 0.5f;
            d = pr[1] - t1; ad = fabsf(d); l += (ad < 1.0f) ? 0.5f * d * d : ad - 0.5f;
            d = pr[2] - t2; ad = fabsf(d); l += (ad < 1.0f) ? 0.5f * d * d : ad - 0.5f;
            d = pr[3] - t3; ad = fabsf(d); l += (ad < 1.0f) ? 0.5f * d * d : ad - 0.5f;
            s += l * WL;
        }
        for (int i = tid; i < 3 * K_; i += T1) {
            int a = neg_idx[n * 3 * K_ + i];
            float p = map_class[n * A_ + a];
            p = fminf(fmaxf(p, EPS), 1.0f - EPS);
            s += -lg2f_(1.0f - p) * (LN2 * WN);
        }
        partial = s;
    }

    // ===== block reduction =====
    red[tid] = partial;
    __syncthreads();
#pragma unroll
    for (int st = T1 / 2; st > 0; st >>= 1) {
        if (tid < st) red[tid] += red[tid + st];
        __syncthreads();
    }
    if (tid == 0) g_partials[bid] = red[0];

    // ===== last-block final reduction =====
    __shared__ bool isLast;
    if (tid == 0) {
        __threadfence();
        unsigned int old = atomicAdd(&g_count, 1u);
        isLast = (old == NPART - 1);
    }
    __syncthreads();
    if (isLast) {
        float s = 0.0f;
        for (int i = tid; i < NPART; i += T1) s += g_partials[i];
        red[tid] = s;
        __syncthreads();
#pragma unroll
        for (int st = T1 / 2; st > 0; st >>= 1) {
            if (tid < st) red[tid] += red[tid + st];
            __syncthreads();
        }
        if (tid == 0) {
            out[0] = red[0];
            g_count = 0;
        }
    }
}

extern "C" void kernel_launch(void* const* d_in, const int* in_sizes, int n_in,
                              void* d_out, int out_size)
{
    const float* map_class     = (const float*)d_in[0];
    const float* map_box       = (const float*)d_in[1];
    const float* map_coef      = (const float*)d_in[2];
    const float* proto         = (const float*)d_in[3];
    const float* anchor_center = (const float*)d_in[4];
    const float* anchor_hw     = (const float*)d_in[5];
    const float* gt_boxes      = (const float*)d_in[6];
    const float* gt_masks      = (const float*)d_in[7];
    const int*   pos_idx       = (const int*)d_in[8];
    const int*   neg_idx       = (const int*)d_in[9];
    const int*   gt_idx        = (const int*)d_in[10];
    float* out = (float*)d_out;

    allloss_kernel<<<NPART, T1>>>(map_class, map_box, map_coef, proto,
                                  anchor_center, anchor_hw, gt_boxes, gt_masks,
                                  pos_idx, neg_idx, gt_idx, out);
}